// round 13
// baseline (speedup 1.0000x reference)
#include <cuda_runtime.h>
#include <cuda_bf16.h>

#define RM_EPS 1e-10f
#define MIN_DEPTH 0.1f
#define MAX_DEPTH 100.0f

constexpr int S_SAMP = 128;        // samples per ray
constexpr int S_INT  = S_SAMP - 1; // 127 intervals
constexpr int WARPS_PER_BLOCK = 8;
constexpr int THREADS_PER_BLOCK = WARPS_PER_BLOCK * 32;

// XOR-swizzled physical slot: conflict-free for blocked access (i=4l+k)
// AND strided access (i=lane+32m).
__device__ __forceinline__ int swz(int i) {
    return (i & ~3) | (((i & 3) + (i >> 5)) & 3);
}

// One warp per ray, BLOCKED lane mapping (lane l owns samples 4l..4l+3,
// float4 loads). Register-lean schedule for 8 blocks/SM:
//   - alpha & dmid staged to swizzled smem immediately (freed from regs)
//   - color LDGs issued after alpha math, latency hidden under the scan
//   - single 5-step warp shfl cumprod scan
//   - per-interval outputs flushed via smem transpose -> coalesced __stcs
__global__ __launch_bounds__(THREADS_PER_BLOCK, 8)
void mip_ray_marcher_kernel(const float* __restrict__ colors,
                            const float* __restrict__ dlog,
                            const float* __restrict__ depths,
                            float* __restrict__ out,
                            int n_rays)
{
    // [warp][stream (w,a,dm)][128 slots]
    __shared__ float stage[WARPS_PER_BLOCK][3][S_SAMP];

    const unsigned FULL = 0xffffffffu;
    const int lane = threadIdx.x & 31;
    const int warp = threadIdx.x >> 5;
    const int ray  = (blockIdx.x * THREADS_PER_BLOCK + threadIdx.x) >> 5;
    if (ray >= n_rays) return;

    float* sw  = stage[warp][0];
    float* sa  = stage[warp][1];
    float* sdm = stage[warp][2];

    // ---- dl/depth loads (2 x LDG.128) ----
    const float4* dl4p = (const float4*)(dlog   + (size_t)ray * S_SAMP);
    const float4* dp4p = (const float4*)(depths + (size_t)ray * S_SAMP);
    float4 dl4 = __ldcs(dl4p + lane);        // samples 4l..4l+3
    float4 dp4 = __ldcs(dp4p + lane);

    // neighbor sample 4l+4 (next lane's .x); lane31's is dead (interval 127 invalid)
    float dl_nx = __shfl_down_sync(FULL, dl4.x, 1);
    float dp_nx = __shfl_down_sync(FULL, dp4.x, 1);

    const float dlv[4] = {dl4.x, dl4.y, dl4.z, dl4.w};
    const float dpv[4] = {dp4.x, dp4.y, dp4.z, dp4.w};
    const float dln[4] = {dl4.y, dl4.z, dl4.w, dl_nx};
    const float dpn[4] = {dp4.y, dp4.z, dp4.w, dp_nx};

    // ---- alpha / (1-alpha+eps) / dmid; stage alpha & dmid to smem NOW ----
    float om[4];
    #pragma unroll
    for (int k = 0; k < 4; k++) {
        const bool valid = !(lane == 31 && k == 3);   // interval 127 doesn't exist
        float dlm  = 0.5f * (dlv[k] + dln[k]) - 1.0f;
        float dens = __logf(1.0f + __expf(dlm));      // softplus
        float a    = 1.0f - __expf(-dens * (dpn[k] - dpv[k]));
        a = valid ? a : 0.0f;
        om[k] = valid ? (1.0f - a + RM_EPS) : 1.0f;   // scan identity
        const int ps = swz(4 * lane + k);
        sa [ps] = a;
        sdm[ps] = 0.5f * (dpv[k] + dpn[k]);
    }

    // ---- color loads issued here: latency overlaps the scan ----
    const float4* c4p = (const float4*)(colors + (size_t)ray * (S_SAMP * 3));
    float4 c0 = __ldcs(c4p + 3 * lane);      // 12 color floats of samples 4l..4l+3
    float4 c1 = __ldcs(c4p + 3 * lane + 1);
    float4 c2 = __ldcs(c4p + 3 * lane + 2);

    // ---- cumprod: local product -> single 5-step warp scan ----
    float incl = om[0] * om[1] * om[2] * om[3];
    #pragma unroll
    for (int off = 1; off < 32; off <<= 1) {
        float v = __shfl_up_sync(FULL, incl, off);
        if (lane >= off) incl *= v;
    }
    float T = __shfl_up_sync(FULL, incl, 1);   // exclusive prefix
    if (lane == 0) T = 1.0f;

    // ---- weights (sequential within lane); alpha/dmid read back from smem
    //      (same-thread RAW on same addresses: no sync needed) ----
    float wt[4];
    float wsum = 0.f, wdsum = 0.f;
    #pragma unroll
    for (int k = 0; k < 4; k++) {
        const bool valid = !(lane == 31 && k == 3);
        const int ps = swz(4 * lane + k);
        float av = sa[ps];
        wt[k] = valid ? (av + RM_EPS) * T : 0.0f;  // exact 0 for regroup
        T *= om[k];
        wsum  += wt[k];
        wdsum += wt[k] * sdm[ps];
    }

    // regrouped color composite: h_s = (w_{s-1} + w_s)/2, w_{-1}=w_127=0
    float wprev = __shfl_up_sync(FULL, wt[3], 1);
    if (lane == 0) wprev = 0.0f;
    float h0 = 0.5f * (wprev + wt[0]);
    float h1 = 0.5f * (wt[0] + wt[1]);
    float h2 = 0.5f * (wt[1] + wt[2]);
    float h3 = 0.5f * (wt[2] + wt[3]);

    // sample colors: s0=(c0.x,c0.y,c0.z) s1=(c0.w,c1.x,c1.y)
    //                s2=(c1.z,c1.w,c2.x) s3=(c2.y,c2.z,c2.w)
    float r0 = h0*c0.x + h1*c0.w + h2*c1.z + h3*c2.y;
    float r1 = h0*c0.y + h1*c1.x + h2*c1.w + h3*c2.z;
    float r2 = h0*c0.z + h1*c1.y + h2*c2.x + h3*c2.w;

    // ---- stage wt, then transpose-read strided + coalesced stores ----
    #pragma unroll
    for (int k = 0; k < 4; k++) sw[swz(4 * lane + k)] = wt[k];
    __syncwarp();

    const size_t NR      = (size_t)n_rays;
    const size_t OFF_RGB = 0;
    const size_t OFF_D   = 3 * NR;
    const size_t OFF_W   = 4 * NR;
    const size_t OFF_WA  = OFF_W  + NR * S_INT;
    const size_t OFF_A   = OFF_WA + NR * S_INT;
    const size_t OFF_DM  = OFF_A  + NR * S_INT;
    const size_t rb      = (size_t)ray * S_INT;

    #pragma unroll
    for (int k = 0; k < 4; k++) {
        const int i = lane + 32 * k;
        if (i < S_INT) {
            const int ps = swz(i);
            float wv  = sw [ps];
            float av  = sa [ps];
            float dmv = sdm[ps];
            __stcs(out + OFF_W  + rb + i, wv);
            __stcs(out + OFF_WA + rb + i, wv);
            __stcs(out + OFF_A  + rb + i, av);
            __stcs(out + OFF_DM + rb + i, dmv);
        }
    }

    // ---- warp reductions (5 scalars) ----
    #pragma unroll
    for (int off = 16; off; off >>= 1) {
        wsum  += __shfl_xor_sync(FULL, wsum, off);
        wdsum += __shfl_xor_sync(FULL, wdsum, off);
        r0    += __shfl_xor_sync(FULL, r0, off);
        r1    += __shfl_xor_sync(FULL, r1, off);
        r2    += __shfl_xor_sync(FULL, r2, off);
    }

    if (lane == 0) {
        out[OFF_RGB + (size_t)ray * 3 + 0] = r0 * 2.0f - 1.0f;
        out[OFF_RGB + (size_t)ray * 3 + 1] = r1 * 2.0f - 1.0f;
        out[OFF_RGB + (size_t)ray * 3 + 2] = r2 * 2.0f - 1.0f;
        float d = wdsum / (RM_EPS + wsum);
        if (!(d == d)) d = MAX_DEPTH;               // nan_to_num
        d = fminf(fmaxf(d, MIN_DEPTH), MAX_DEPTH);  // clip
        out[OFF_D + ray] = d;
    }
}

extern "C" void kernel_launch(void* const* d_in, const int* in_sizes, int n_in,
                              void* d_out, int out_size)
{
    const float* colors = (const float*)d_in[0];  // [B,R,S,3]
    const float* dlog   = (const float*)d_in[1];  // [B,R,S,1]
    const float* depths = (const float*)d_in[2];  // [B,R,S,1]
    float* out = (float*)d_out;

    int n_rays = in_sizes[1] / S_SAMP;            // B*R = 65536
    int blocks = (n_rays + WARPS_PER_BLOCK - 1) / WARPS_PER_BLOCK;
    mip_ray_marcher_kernel<<<blocks, THREADS_PER_BLOCK>>>(
        colors, dlog, depths, out, n_rays);
}

// round 14
// speedup vs baseline: 1.2547x; 1.2547x over previous
#include <cuda_runtime.h>
#include <cuda_bf16.h>

#define RM_EPS 1e-10f
#define MIN_DEPTH 0.1f
#define MAX_DEPTH 100.0f

constexpr int S_SAMP = 128;        // samples per ray
constexpr int S_INT  = S_SAMP - 1; // 127 intervals
constexpr int WARPS_PER_BLOCK = 4;
constexpr int THREADS_PER_BLOCK = WARPS_PER_BLOCK * 32;

// XOR-swizzled physical slot: conflict-free for blocked writes (i=4l+k)
// AND strided reads (i=lane+32m).
__device__ __forceinline__ int swz(int i) {
    return (i & ~3) | (((i & 3) + (i >> 5)) & 3);
}

// One warp per ray, BLOCKED lane mapping: lane l owns samples/intervals
// 4l..4l+3 via float4 loads (5 LDG.128/thread, front-issued). Neighbors
// in-register (one shfl_down each for dl/depth). Cumprod = local 4-product
// + single 5-step warp scan + 4 sequential in-lane steps. Per-interval
// outputs go blocked->strided through a swizzled per-warp smem transpose so
// global stores stay perfectly coalesced. 4 warps/block for regfile-limited
// 13 blocks/SM (52 warps/SM vs 48 at block=256).
__global__ __launch_bounds__(THREADS_PER_BLOCK)
void mip_ray_marcher_kernel(const float* __restrict__ colors,
                            const float* __restrict__ dlog,
                            const float* __restrict__ depths,
                            float* __restrict__ out,
                            int n_rays)
{
    // [warp][stream (w,a,dm)][128 slots]
    __shared__ float stage[WARPS_PER_BLOCK][3][S_SAMP];

    const unsigned FULL = 0xffffffffu;
    const int lane = threadIdx.x & 31;
    const int warp = threadIdx.x >> 5;
    const int ray  = (blockIdx.x * THREADS_PER_BLOCK + threadIdx.x) >> 5;
    if (ray >= n_rays) return;

    // ---- front-load everything: 5 x LDG.128 per thread ----
    const float4* dl4p = (const float4*)(dlog   + (size_t)ray * S_SAMP);
    const float4* dp4p = (const float4*)(depths + (size_t)ray * S_SAMP);
    const float4* c4p  = (const float4*)(colors + (size_t)ray * (S_SAMP * 3));

    float4 dl4 = __ldcs(dl4p + lane);        // samples 4l..4l+3
    float4 dp4 = __ldcs(dp4p + lane);
    float4 c0  = __ldcs(c4p + 3 * lane);     // 12 color floats of samples 4l..4l+3
    float4 c1  = __ldcs(c4p + 3 * lane + 1);
    float4 c2  = __ldcs(c4p + 3 * lane + 2);

    // neighbor sample 4l+4 (next lane's .x); lane31's is dead (interval 127 invalid)
    float dl_nx = __shfl_down_sync(FULL, dl4.x, 1);
    float dp_nx = __shfl_down_sync(FULL, dp4.x, 1);

    const float dlv[4] = {dl4.x, dl4.y, dl4.z, dl4.w};
    const float dpv[4] = {dp4.x, dp4.y, dp4.z, dp4.w};
    const float dln[4] = {dl4.y, dl4.z, dl4.w, dl_nx};
    const float dpn[4] = {dp4.y, dp4.z, dp4.w, dp_nx};

    // ---- alpha / (1-alpha+eps) / dmid per interval (MUFU fast math) ----
    float aarr[4], om[4], dmid[4];
    #pragma unroll
    for (int k = 0; k < 4; k++) {
        const bool valid = !(lane == 31 && k == 3);   // interval 127 doesn't exist
        float dlm  = 0.5f * (dlv[k] + dln[k]) - 1.0f;
        float dens = __logf(1.0f + __expf(dlm));      // softplus
        float a    = 1.0f - __expf(-dens * (dpn[k] - dpv[k]));
        aarr[k] = valid ? a : 0.0f;
        om[k]   = valid ? (1.0f - a + RM_EPS) : 1.0f; // scan identity
        dmid[k] = 0.5f * (dpv[k] + dpn[k]);
    }

    // ---- cumprod: local product -> single 5-step warp scan ----
    float p = om[0] * om[1] * om[2] * om[3];
    float incl = p;
    #pragma unroll
    for (int off = 1; off < 32; off <<= 1) {
        float v = __shfl_up_sync(FULL, incl, off);
        if (lane >= off) incl *= v;
    }
    float T = __shfl_up_sync(FULL, incl, 1);   // exclusive prefix
    if (lane == 0) T = 1.0f;

    // ---- weights (sequential within lane) ----
    float wt[4];
    #pragma unroll
    for (int k = 0; k < 4; k++) {
        const bool valid = !(lane == 31 && k == 3);
        wt[k] = valid ? (aarr[k] + RM_EPS) * T : 0.0f;  // exact 0 for regroup
        T *= om[k];
    }

    // ---- scalar composites ----
    float wsum  = wt[0] + wt[1] + wt[2] + wt[3];
    float wdsum = wt[0]*dmid[0] + wt[1]*dmid[1] + wt[2]*dmid[2] + wt[3]*dmid[3];

    // regrouped color composite: h_s = (w_{s-1} + w_s)/2, w_{-1}=w_127=0
    float wprev = __shfl_up_sync(FULL, wt[3], 1);
    if (lane == 0) wprev = 0.0f;
    float h0 = 0.5f * (wprev + wt[0]);
    float h1 = 0.5f * (wt[0] + wt[1]);
    float h2 = 0.5f * (wt[1] + wt[2]);
    float h3 = 0.5f * (wt[2] + wt[3]);

    // sample colors: s0=(c0.x,c0.y,c0.z) s1=(c0.w,c1.x,c1.y)
    //                s2=(c1.z,c1.w,c2.x) s3=(c2.y,c2.z,c2.w)
    float r0 = h0*c0.x + h1*c0.w + h2*c1.z + h3*c2.y;
    float r1 = h0*c0.y + h1*c1.x + h2*c1.w + h3*c2.z;
    float r2 = h0*c0.z + h1*c1.y + h2*c2.x + h3*c2.w;

    // ---- blocked writes into swizzled per-warp smem stage ----
    float* sw  = stage[warp][0];
    float* sa  = stage[warp][1];
    float* sdm = stage[warp][2];
    #pragma unroll
    for (int k = 0; k < 4; k++) {
        const int ps = swz(4 * lane + k);
        sw [ps] = wt[k];
        sa [ps] = aarr[k];
        sdm[ps] = dmid[k];
    }
    __syncwarp();

    // ---- output offsets (flattened tuple, float32) ----
    const size_t NR      = (size_t)n_rays;
    const size_t OFF_RGB = 0;
    const size_t OFF_D   = 3 * NR;
    const size_t OFF_W   = 4 * NR;
    const size_t OFF_WA  = OFF_W  + NR * S_INT;
    const size_t OFF_A   = OFF_WA + NR * S_INT;
    const size_t OFF_DM  = OFF_A  + NR * S_INT;
    const size_t rb      = (size_t)ray * S_INT;

    // ---- strided reads from stage + coalesced streaming stores ----
    #pragma unroll
    for (int k = 0; k < 4; k++) {
        const int i = lane + 32 * k;
        if (i < S_INT) {
            const int ps = swz(i);
            float wv  = sw [ps];
            float av  = sa [ps];
            float dmv = sdm[ps];
            __stcs(out + OFF_W  + rb + i, wv);
            __stcs(out + OFF_WA + rb + i, wv);
            __stcs(out + OFF_A  + rb + i, av);
            __stcs(out + OFF_DM + rb + i, dmv);
        }
    }

    // ---- warp reductions (5 scalars) ----
    #pragma unroll
    for (int off = 16; off; off >>= 1) {
        wsum  += __shfl_xor_sync(FULL, wsum, off);
        wdsum += __shfl_xor_sync(FULL, wdsum, off);
        r0    += __shfl_xor_sync(FULL, r0, off);
        r1    += __shfl_xor_sync(FULL, r1, off);
        r2    += __shfl_xor_sync(FULL, r2, off);
    }

    if (lane == 0) {
        out[OFF_RGB + (size_t)ray * 3 + 0] = r0 * 2.0f - 1.0f;
        out[OFF_RGB + (size_t)ray * 3 + 1] = r1 * 2.0f - 1.0f;
        out[OFF_RGB + (size_t)ray * 3 + 2] = r2 * 2.0f - 1.0f;
        float d = wdsum / (RM_EPS + wsum);
        if (!(d == d)) d = MAX_DEPTH;               // nan_to_num
        d = fminf(fmaxf(d, MIN_DEPTH), MAX_DEPTH);  // clip
        out[OFF_D + ray] = d;
    }
}

extern "C" void kernel_launch(void* const* d_in, const int* in_sizes, int n_in,
                              void* d_out, int out_size)
{
    const float* colors = (const float*)d_in[0];  // [B,R,S,3]
    const float* dlog   = (const float*)d_in[1];  // [B,R,S,1]
    const float* depths = (const float*)d_in[2];  // [B,R,S,1]
    float* out = (float*)d_out;

    int n_rays = in_sizes[1] / S_SAMP;            // B*R = 65536
    int blocks = (n_rays + WARPS_PER_BLOCK - 1) / WARPS_PER_BLOCK;
    mip_ray_marcher_kernel<<<blocks, THREADS_PER_BLOCK>>>(
        colors, dlog, depths, out, n_rays);
}